// round 15
// baseline (speedup 1.0000x reference)
#include <cuda_runtime.h>
#include <cuda_bf16.h>
#include <cuda_fp16.h>
#include <cstdint>

#define B_    4
#define N_    2048
#define FIN_  512
#define FOUT_ 128
#define ROWS_TOT (B_ * N_)
#define PX    144
#define PW    272
#define PB2   144    // attn B tile pitch
#define TROWS 136    // 128 h rows + 1 ones row + 7 zero pad
#define TILE_B (TROWS * PB2)   // 19584

// ---------------- global scratch (no cudaMalloc allowed) --------------------
__device__ __align__(16) __nv_bfloat16 g_WH[FIN_ * FOUT_];  // W hi [k][n]
__device__ __align__(16) __nv_bfloat16 g_WL[FIN_ * FOUT_];  // W lo [k][n]
__device__ __align__(16) __half g_hH[B_ * TROWS * N_];  // [b][o][j] h fp16; row128=1
__device__ __align__(16) __half g_e2h[ROWS_TOT], g_f2h[ROWS_TOT];  // 0.25*E2/F2
__device__ __half g_e1h[ROWS_TOT], g_f1h[ROWS_TOT];                // 0.25*E1/F1
__device__ float g_t1[ROWS_TOT], g_t2[ROWS_TOT];
__device__ __align__(16) float g_part[2][ROWS_TOT * FOUT_];
__device__ float g_den[2][ROWS_TOT];
__device__ int   g_cnt[B_ * 32];

// ---------------- helpers ----------------------------------------------------
__device__ __forceinline__ void mma_bf16(float* c,
    uint32_t a0, uint32_t a1, uint32_t a2, uint32_t a3, uint32_t b0, uint32_t b1) {
    asm volatile(
        "mma.sync.aligned.m16n8k16.row.col.f32.bf16.bf16.f32 "
        "{%0,%1,%2,%3},{%4,%5,%6,%7},{%8,%9},{%0,%1,%2,%3};"
        : "+f"(c[0]), "+f"(c[1]), "+f"(c[2]), "+f"(c[3])
        : "r"(a0), "r"(a1), "r"(a2), "r"(a3), "r"(b0), "r"(b1));
}
__device__ __forceinline__ void mma_f16(float* c,
    uint32_t a0, uint32_t a1, uint32_t a2, uint32_t a3, uint32_t b0, uint32_t b1) {
    asm volatile(
        "mma.sync.aligned.m16n8k16.row.col.f32.f16.f16.f32 "
        "{%0,%1,%2,%3},{%4,%5,%6,%7},{%8,%9},{%0,%1,%2,%3};"
        : "+f"(c[0]), "+f"(c[1]), "+f"(c[2]), "+f"(c[3])
        : "r"(a0), "r"(a1), "r"(a2), "r"(a3), "r"(b0), "r"(b1));
}
#define LDM4(r0, r1, r2, r3, a)                                          \
    asm volatile("ldmatrix.sync.aligned.m8n8.x4.shared.b16 "             \
                 "{%0,%1,%2,%3},[%4];"                                   \
                 : "=r"(r0), "=r"(r1), "=r"(r2), "=r"(r3) : "r"(a))
#define LDM4T(r0, r1, r2, r3, a)                                         \
    asm volatile("ldmatrix.sync.aligned.m8n8.x4.trans.shared.b16 "       \
                 "{%0,%1,%2,%3},[%4];"                                   \
                 : "=r"(r0), "=r"(r1), "=r"(r2), "=r"(r3) : "r"(a))
__device__ __forceinline__ uint32_t bf2u(__nv_bfloat162 v) {
    return *reinterpret_cast<uint32_t*>(&v);
}
__device__ __forceinline__ void split2(float a, float b, uint32_t& hi, uint32_t& lo) {
    __nv_bfloat162 h = __floats2bfloat162_rn(a, b);
    __nv_bfloat162 l = __floats2bfloat162_rn(a - __bfloat162float(h.x),
                                             b - __bfloat162float(h.y));
    hi = bf2u(h); lo = bf2u(l);
}
__device__ __forceinline__ uint32_t h2u(__half2 v) {
    return *reinterpret_cast<uint32_t*>(&v);
}
#define CPASYNC16(dst, src) \
    asm volatile("cp.async.cg.shared.global [%0], [%1], 16;" :: "r"(dst), "l"(src))
#define CPCOMMIT() asm volatile("cp.async.commit_group;" ::: "memory")
#define CPWAIT(n)  asm volatile("cp.async.wait_group %0;" :: "n"(n) : "memory")
__device__ __forceinline__ uint32_t smem_u32(const void* p) {
    uint32_t a;
    asm("{ .reg .u64 t; cvta.to.shared.u64 t, %1; cvt.u32.u64 %0, t; }"
        : "=r"(a) : "l"(p));
    return a;
}

// ---------------------------------------------------------------------------
// K0: W fp32 [k][n] -> bf16 hi/lo [k][n] (one-shot split; layout unchanged)
// ---------------------------------------------------------------------------
__global__ __launch_bounds__(256) void k_wprep(const float* __restrict__ W) {
    int f = blockIdx.x * 256 + threadIdx.x;   // 16384 float4 total
    float4 v = *(const float4*)(W + f * 4);
    uint32_t h0, l0, h1, l1;
    split2(v.x, v.y, h0, l0);
    split2(v.z, v.w, h1, l1);
    *(uint2*)(g_WH + f * 4) = make_uint2(h0, h1);
    *(uint2*)(g_WL + f * 4) = make_uint2(l0, l1);
}

// ---------------------------------------------------------------------------
// K1: h = X @ W (bf16 hi/lo 3-MMA). R13 tile shape (64 rows, 256 thr,
// grid 128); W pre-split, fetched via cp.async (no per-CTA W splitting).
// ---------------------------------------------------------------------------
#define GXH 0
#define GXL 9216
#define GWH 18432
#define GWL 35840
#define GA1 53248
#define GA2 53760
#define GSM 54272

__global__ __launch_bounds__(256) void k_gemm_tc(const float* __restrict__ X,
                                                 const float* __restrict__ a1,
                                                 const float* __restrict__ a2) {
    extern __shared__ char sm[];
    const uint32_t smb = smem_u32(sm);
    const int t = threadIdx.x, w = t >> 5, lane = t & 31;
    const int wm = w & 3, wn = w >> 2;
    const int row0 = blockIdx.x * 64;

    if (t < 128) {
        ((float*)(sm + GA1))[t] = a1[t];
        ((float*)(sm + GA2))[t] = a2[t];
    }

    float acc[8][4];
#pragma unroll
    for (int nt = 0; nt < 8; nt++)
        acc[nt][0] = acc[nt][1] = acc[nt][2] = acc[nt][3] = 0.f;

    const uint32_t ax_off =
        (uint32_t)(wm * 16 + ((lane >> 3) & 1) * 8 + (lane & 7)) * PX +
        (lane >> 4) * 16;
    const uint32_t wl_row = (uint32_t)lane * PW;

    for (int c = 0; c < 8; c++) {
        const int kc = c * 64;
        // W tiles via cp.async: 64 k x 16 vec x 2 mats = 2048 vec / 256 thr
#pragma unroll
        for (int l = 0; l < 8; l++) {
            int f = t + l * 256;
            int mat = f >= 1024;
            int idx = f - (mat ? 1024 : 0);
            int k = idx >> 4, u = idx & 15;
            const __nv_bfloat16* src = (mat ? g_WL : g_WH) +
                                       (size_t)(kc + k) * FOUT_ + u * 8;
            uint32_t dst = smb + (mat ? GWL : GWH) + k * PW + u * 16;
            CPASYNC16(dst, src);
        }
        CPCOMMIT();
        // X tile: 64 rows x 64 k fp32 -> bf16 hi/lo (overlaps W DMA)
#pragma unroll
        for (int l = 0; l < 4; l++) {
            int f = t + l * 256;
            int m = f >> 4, kq = (f & 15) * 4;
            float4 v = *(const float4*)(X + (size_t)(row0 + m) * FIN_ + kc + kq);
            uint32_t h0, l0, h1, l1;
            split2(v.x, v.y, h0, l0);
            split2(v.z, v.w, h1, l1);
            *(uint2*)(sm + GXH + m * PX + kq * 2) = make_uint2(h0, h1);
            *(uint2*)(sm + GXL + m * PX + kq * 2) = make_uint2(l0, l1);
        }
        CPWAIT(0);
        __syncthreads();

        uint32_t ah[4][4], al[4][4];
#pragma unroll
        for (int ks = 0; ks < 4; ks++) {
            LDM4(ah[ks][0], ah[ks][1], ah[ks][2], ah[ks][3],
                 smb + GXH + ax_off + ks * 32);
            LDM4(al[ks][0], al[ks][1], al[ks][2], al[ks][3],
                 smb + GXL + ax_off + ks * 32);
        }
#pragma unroll
        for (int nt = 0; nt < 8; nt++) {
            const int n0 = wn * 64 + nt * 8;
            const uint32_t wadr = smb + GWH + wl_row + n0 * 2;
            uint32_t bh[8], bl[8];
            LDM4T(bh[0], bh[1], bh[2], bh[3], wadr);
            LDM4T(bh[4], bh[5], bh[6], bh[7], wadr + 32 * PW);
            LDM4T(bl[0], bl[1], bl[2], bl[3], wadr + (GWL - GWH));
            LDM4T(bl[4], bl[5], bl[6], bl[7], wadr + (GWL - GWH) + 32 * PW);
#pragma unroll
            for (int ks = 0; ks < 4; ks++) {
                mma_bf16(acc[nt], ah[ks][0], ah[ks][1], ah[ks][2], ah[ks][3],
                         bh[2 * ks], bh[2 * ks + 1]);
                mma_bf16(acc[nt], ah[ks][0], ah[ks][1], ah[ks][2], ah[ks][3],
                         bl[2 * ks], bl[2 * ks + 1]);
                mma_bf16(acc[nt], al[ks][0], al[ks][1], al[ks][2], al[ks][3],
                         bh[2 * ks], bh[2 * ks + 1]);
            }
        }
        __syncthreads();
    }

    // ---- epilogue (R13 verbatim) ----
    const int g = lane >> 2, tig = lane & 3;
    float* Ds = (float*)sm;
    {
        const int r = wm * 16 + g, cl = wn * 64 + 2 * tig;
#pragma unroll
        for (int nt = 0; nt < 8; nt++) {
            Ds[r * 132 + cl + nt * 8]           = acc[nt][0];
            Ds[r * 132 + cl + nt * 8 + 1]       = acc[nt][1];
            Ds[(r + 8) * 132 + cl + nt * 8]     = acc[nt][2];
            Ds[(r + 8) * 132 + cl + nt * 8 + 1] = acc[nt][3];
        }
    }
    __syncthreads();
    const float* A1 = (const float*)(sm + GA1);
    const float* A2 = (const float*)(sm + GA2);
#pragma unroll
    for (int rr = 0; rr < 8; rr++) {
        int r = w * 8 + rr;
        float s1 = 0.f, s2 = 0.f;
#pragma unroll
        for (int q = 0; q < 4; q++) {
            float v = Ds[r * 132 + lane + 32 * q];
            s1 = fmaf(v, A1[lane + 32 * q], s1);
            s2 = fmaf(v, A2[lane + 32 * q], s2);
        }
#pragma unroll
        for (int o = 16; o; o >>= 1) {
            s1 += __shfl_down_sync(0xffffffffu, s1, o);
            s2 += __shfl_down_sync(0xffffffffu, s2, o);
        }
        if (lane == 0) {
            int gr = row0 + r;
            g_t1[gr] = s1;  g_t2[gr] = s2;
            g_e1h[gr] = __float2half_rn(0.25f * expf(s1));
            g_f1h[gr] = __float2half_rn(0.25f * expf(0.2f * s1));
            g_e2h[gr] = __float2half_rn(0.25f * expf(s2));
            g_f2h[gr] = __float2half_rn(0.25f * expf(0.2f * s2));
        }
    }
    __syncthreads();
    {
        const int o = t & 127, half = t >> 7;
        const int bb = row0 >> 11, j0g = row0 & (N_ - 1);
        uint32_t uH[16];
#pragma unroll
        for (int ii = 0; ii < 16; ii++) {
            int j0l = half * 32 + 2 * ii;
            uH[ii] = h2u(__floats2half2_rn(Ds[j0l * 132 + o],
                                           Ds[(j0l + 1) * 132 + o]));
        }
        size_t base = ((size_t)(bb * TROWS) + o) * N_ + j0g + half * 32;
#pragma unroll
        for (int q = 0; q < 4; q++)
            *(uint4*)(g_hH + base + q * 8) =
                make_uint4(uH[4 * q], uH[4 * q + 1], uH[4 * q + 2], uH[4 * q + 3]);
        if (t < 64)
            g_hH[((size_t)(bb * TROWS) + 128) * N_ + j0g + t] = __float2half_rn(1.0f);
    }
}

// ---------------------------------------------------------------------------
// K2: attention (R13 verbatim): single fp16-P GEMM [D|den] = P @ [h;1],
// warp grid 2(m) x 4(n), cooperative expand, j-split x2 + in-kernel combine.
// ---------------------------------------------------------------------------
#define ASTG (2 * TILE_B)           // 39168
#define APB  144
#define ASZ  (64 * APB)             // 9216
#define ST2  (ASTG + 2 * ASZ)       // 57600: t2 fp32 [1024]
#define SE2  (ST2 + 4096)           // 61696: 0.25*E2 fp16 [1024]
#define SF2  (SE2 + 2048)           // 63744: 0.25*F2 fp16 [1024]
#define ASM2 (SF2 + 2048)           // 65792 total dynamic

__global__ __launch_bounds__(256, 2) void k_attn_tc(const int* __restrict__ adj,
                                                    const int* __restrict__ d1p,
                                                    const int* __restrict__ d2p,
                                                    float* __restrict__ out) {
    extern __shared__ char sm[];
    __shared__ float s_den[64];
    __shared__ int s_old;
    const uint32_t smb = smem_u32(sm);
    const int t = threadIdx.x, w = t >> 5, lane = t & 31;
    const int g = lane >> 2, tig = lane & 3;
    const int wm = w & 1, wn = w >> 1;
    const int tile = blockIdx.x >> 1, jh = blockIdx.x & 1;
    const int b = tile >> 5, i0 = (tile & 31) * 64;
    const int jbase = jh * 1024;
    const int d1 = *d1p, d2 = *d2p;

    const __half* gHb = g_hH + (size_t)b * TROWS * N_;

    auto load_chunk = [&](int j0, int buf) {
#pragma unroll
        for (int l = 0; l < 5; l++) {
            int f = t + l * 256;
            if (f < 1088) {
                int row = f >> 3, u = f & 7;
                const __half* src = gHb + (size_t)row * N_ + j0 + u * 8;
                uint32_t dst = smb + buf * TILE_B + row * PB2 + u * 16;
                CPASYNC16(dst, src);
            }
        }
    };

    load_chunk(jbase, 0);
    CPCOMMIT();

    // ---- tables into smem ----
    ((float4*)(sm + ST2))[t] = ((const float4*)(g_t2 + b * N_ + jbase))[t];
    if (t < 128)
        ((uint4*)(sm + SE2))[t] = ((const uint4*)(g_e2h + b * N_ + jbase))[t];
    else
        ((uint4*)(sm + SF2))[t - 128] =
            ((const uint4*)(g_f2h + b * N_ + jbase))[t - 128];

    // ---- expansion row constants ----
    const int rexp = t >> 2, ctexp = t & 3;
    const int gadj = b * N_ + i0 + rexp;
    const float nt1r = -g_t1[gadj];
    const uint32_t e1lo = (uint32_t)__half_as_ushort(g_e1h[gadj]);
    const uint32_t f1lo = (uint32_t)__half_as_ushort(g_f1h[gadj]);
    const uint32_t e1hi = e1lo << 16, f1hi = f1lo << 16;
    const int* adjrow = adj + (size_t)gadj * N_ + jbase + ctexp * 16;

    auto expand = [&](int4 q0, int4 q1, int4 q2, int4 q3, int cc, int ab) {
        const int jl = cc * 64 + ctexp * 16;
        const float* tp = (const float*)(sm + ST2) + jl;
        float4 t0 = *(const float4*)(tp);
        float4 t1v = *(const float4*)(tp + 4);
        float4 t2v = *(const float4*)(tp + 8);
        float4 t3 = *(const float4*)(tp + 12);
        float tf[16] = {t0.x, t0.y, t0.z, t0.w, t1v.x, t1v.y, t1v.z, t1v.w,
                        t2v.x, t2v.y, t2v.z, t2v.w, t3.x, t3.y, t3.z, t3.w};
        uint4 ea = *(const uint4*)((const __half*)(sm + SE2) + jl);
        uint4 eb = *(const uint4*)((const __half*)(sm + SE2) + jl + 8);
        uint4 fa = *(const uint4*)((const __half*)(sm + SF2) + jl);
        uint4 fb = *(const uint4*)((const __half*)(sm + SF2) + jl + 8);
        uint32_t UE[8] = {ea.x, ea.y, ea.z, ea.w, eb.x, eb.y, eb.z, eb.w};
        uint32_t UF[8] = {fa.x, fa.y, fa.z, fa.w, fb.x, fb.y, fb.z, fb.w};
        int av[16] = {q0.x, q0.y, q0.z, q0.w, q1.x, q1.y, q1.z, q1.w,
                      q2.x, q2.y, q2.z, q2.w, q3.x, q3.y, q3.z, q3.w};
        uint32_t ow[8];
#pragma unroll
        for (int k = 0; k < 8; k++) {
            int a0 = av[2 * k], a1 = av[2 * k + 1];
            bool m0 = (a0 == d1) | (a0 == d2);
            bool m1 = (a1 == d1) | (a1 == d2);
            bool p0 = tf[2 * k] > nt1r;
            bool p1 = tf[2 * k + 1] > nt1r;
            uint32_t s2 = (p0 ? (UE[k] & 0xffffu) : (UF[k] & 0xffffu))
                        | (p1 ? (UE[k] & 0xffff0000u) : (UF[k] & 0xffff0000u));
            uint32_t s1 = (p0 ? e1lo : f1lo) | (p1 ? e1hi : f1hi);
            __half2 pr = __hmul2(*(__half2*)&s1, *(__half2*)&s2);
            uint32_t z = (m0 ? 0xffffu : 0u) | (m1 ? 0xffff0000u : 0u);
            ow[k] = (*(uint32_t*)&pr) & z;
        }
        char* dst = sm + ASTG + ab * ASZ + rexp * APB + ctexp * 32;
        *(uint4*)(dst)      = make_uint4(ow[0], ow[1], ow[2], ow[3]);
        *(uint4*)(dst + 16) = make_uint4(ow[4], ow[5], ow[6], ow[7]);
    };

    int4 q0 = *(const int4*)(adjrow);
    int4 q1 = *(const int4*)(adjrow + 4);
    int4 q2 = *(const int4*)(adjrow + 8);
    int4 q3 = *(const int4*)(adjrow + 12);

    __syncthreads();
    expand(q0, q1, q2, q3, 0, 0);

    const int ntiles = (wn == 3) ? 5 : 4;
    float acc[2][5][4];
#pragma unroll
    for (int ms = 0; ms < 2; ms++)
#pragma unroll
        for (int k = 0; k < 5; k++)
            acc[ms][k][0] = acc[ms][k][1] = acc[ms][k][2] = acc[ms][k][3] = 0.f;

    const uint32_t bloff = (uint32_t)(lane & 7) * PB2 + (lane >> 3) * 16;
    const uint32_t aloff =
        (uint32_t)((lane & 15) + wm * 32) * APB + (lane >> 4) * 16;

    for (int c = 0; c < 16; c++) {
        const int buf = c & 1;
        CPWAIT(0);
        __syncthreads();
        if (c + 1 < 16) {
            load_chunk(jbase + (c + 1) * 64, buf ^ 1);
            CPCOMMIT();
            const int* ap = adjrow + (c + 1) * 64;
            q0 = *(const int4*)(ap);
            q1 = *(const int4*)(ap + 4);
            q2 = *(const int4*)(ap + 8);
            q3 = *(const int4*)(ap + 12);
        }

        const uint32_t abase = smb + ASTG + buf * ASZ + aloff;
        const uint32_t base = smb + buf * TILE_B + bloff;
#pragma unroll
        for (int ga = 0; ga < 2; ga++) {
            uint32_t aH[2][2][4];
#pragma unroll
            for (int ms = 0; ms < 2; ms++)
#pragma unroll
                for (int k2 = 0; k2 < 2; k2++)
                    LDM4(aH[ms][k2][0], aH[ms][k2][1], aH[ms][k2][2], aH[ms][k2][3],
                         abase + (uint32_t)(ms * 16) * APB + (2 * ga + k2) * 32);

            uint32_t bb[2][4];
            {
                const int gt0 = wn * 4;
                LDM4(bb[0][0], bb[0][1], bb[0][2], bb[0][3],
                     base + (uint32_t)(gt0 * 8) * PB2 + ga * 64);
            }
#pragma unroll
            for (int k = 0; k < 5; k++) {
                if (k >= ntiles) break;
                const int cur = k & 1, nxt = cur ^ 1;
                if (k + 1 < ntiles) {
                    const int gtn = (k + 1 < 4) ? wn * 4 + k + 1 : 16;
                    LDM4(bb[nxt][0], bb[nxt][1], bb[nxt][2], bb[nxt][3],
                         base + (uint32_t)(gtn * 8) * PB2 + ga * 64);
                }
                mma_f16(acc[0][k], aH[0][0][0], aH[0][0][1], aH[0][0][2], aH[0][0][3],
                        bb[cur][0], bb[cur][1]);
                mma_f16(acc[1][k], aH[1][0][0], aH[1][0][1], aH[1][0][2], aH[1][0][3],
                        bb[cur][0], bb[cur][1]);
                mma_f16(acc[0][k], aH[0][1][0], aH[0][1][1], aH[0][1][2], aH[0][1][3],
                        bb[cur][2], bb[cur][3]);
                mma_f16(acc[1][k], aH[1][1][0], aH[1][1][1], aH[1][1][2], aH[1][1][3],
                        bb[cur][2], bb[cur][3]);
            }
        }

        if (c + 1 < 16)
            expand(q0, q1, q2, q3, c + 1, buf ^ 1);
    }

    if (wn == 3 && tig == 0) {
#pragma unroll
        for (int ms = 0; ms < 2; ms++) {
            s_den[wm * 32 + ms * 16 + g]     = acc[ms][4][0];
            s_den[wm * 32 + ms * 16 + g + 8] = acc[ms][4][2];
        }
    }
    __syncthreads();

    float* gp = g_part[jh];
#pragma unroll
    for (int ms = 0; ms < 2; ms++) {
        const int gr0 = b * N_ + i0 + wm * 32 + ms * 16 + g;
        const int gr1 = gr0 + 8;
#pragma unroll
        for (int k = 0; k < 4; k++) {
            const int cl = (wn * 4 + k) * 8 + 2 * tig;
            *(float2*)(gp + (size_t)gr0 * FOUT_ + cl) =
                make_float2(acc[ms][k][0], acc[ms][k][1]);
            *(float2*)(gp + (size_t)gr1 * FOUT_ + cl) =
                make_float2(acc[ms][k][2], acc[ms][k][3]);
        }
    }
    if (t < 64) g_den[jh][b * N_ + i0 + t] = s_den[t];
    __threadfence();
    __syncthreads();
    if (t == 0) s_old = atomicAdd(&g_cnt[tile], 1);
    __syncthreads();

    if (s_old == 1) {
        __threadfence();
        const float* go = g_part[jh ^ 1];
        const float* gdo = g_den[jh ^ 1];
#pragma unroll
        for (int ms = 0; ms < 2; ms++) {
            const int lr0 = wm * 32 + ms * 16 + g;
            const int gr0 = b * N_ + i0 + lr0;
            const int gr1 = gr0 + 8;
            const float inv0 = 1.0f / (s_den[lr0] + gdo[gr0]);
            const float inv1 = 1.0f / (s_den[lr0 + 8] + gdo[gr1]);
#pragma unroll
            for (int k = 0; k < 4; k++) {
                const int cl = (wn * 4 + k) * 8 + 2 * tig;
                float2 o0 = *(const float2*)(go + (size_t)gr0 * FOUT_ + cl);
                float2 o1 = *(const float2*)(go + (size_t)gr1 * FOUT_ + cl);
                *(float2*)(out + (size_t)gr0 * FOUT_ + cl) =
                    make_float2((acc[ms][k][0] + o0.x) * inv0,
                                (acc[ms][k][1] + o0.y) * inv0);
                *(float2*)(out + (size_t)gr1 * FOUT_ + cl) =
                    make_float2((acc[ms][k][2] + o1.x) * inv1,
                                (acc[ms][k][3] + o1.y) * inv1);
            }
        }
        if (t == 0) g_cnt[tile] = 0;
    }
}

// ---------------------------------------------------------------------------
extern "C" void kernel_launch(void* const* d_in, const int* in_sizes, int n_in,
                              void* d_out, int out_size) {
    const float* X   = (const float*)d_in[0];
    const float* W   = (const float*)d_in[1];
    const float* a1  = (const float*)d_in[2];
    const float* a2  = (const float*)d_in[3];
    const int*   adj = (const int*)d_in[4];
    // d_in[5] = adj_tree: unused by the reference forward
    const int* d1p = (const int*)d_in[6];
    const int* d2p = (const int*)d_in[7];
    float* out = (float*)d_out;

    k_wprep<<<FIN_ * FOUT_ / 4 / 256, 256>>>(W);

    cudaFuncSetAttribute(k_gemm_tc, cudaFuncAttributeMaxDynamicSharedMemorySize, GSM);
    k_gemm_tc<<<ROWS_TOT / 64, 256, GSM>>>(X, a1, a2);

    cudaFuncSetAttribute(k_attn_tc, cudaFuncAttributeMaxDynamicSharedMemorySize, ASM2);
    k_attn_tc<<<B_ * 32 * 2, 256, ASM2>>>(adj, d1p, d2p, out);
}

// round 16
// speedup vs baseline: 1.0904x; 1.0904x over previous
#include <cuda_runtime.h>
#include <cuda_bf16.h>
#include <cuda_fp16.h>
#include <cstdint>

#define B_    4
#define N_    2048
#define FIN_  512
#define FOUT_ 128
#define ROWS_TOT (B_ * N_)
#define PX    144
#define PW    272
#define PB2   144    // attn B tile pitch
#define TROWS 136    // 128 h rows + 1 ones row + 7 zero pad
#define TILE_B (TROWS * PB2)   // 19584

// ---------------- global scratch (no cudaMalloc allowed) --------------------
__device__ __align__(16) __half g_hH[B_ * TROWS * N_];  // [b][o][j] h fp16; row128=1
__device__ __align__(16) __half g_e2h[ROWS_TOT], g_f2h[ROWS_TOT];  // 0.25*E2/F2
__device__ __half g_e1h[ROWS_TOT], g_f1h[ROWS_TOT];                // 0.25*E1/F1
__device__ float g_t1[ROWS_TOT], g_t2[ROWS_TOT];
__device__ __align__(16) float g_part[2][ROWS_TOT * FOUT_];
__device__ float g_den[2][ROWS_TOT];
__device__ int   g_cnt[B_ * 32];

// ---------------- helpers ----------------------------------------------------
__device__ __forceinline__ void mma_bf16(float* c,
    uint32_t a0, uint32_t a1, uint32_t a2, uint32_t a3, uint32_t b0, uint32_t b1) {
    asm volatile(
        "mma.sync.aligned.m16n8k16.row.col.f32.bf16.bf16.f32 "
        "{%0,%1,%2,%3},{%4,%5,%6,%7},{%8,%9},{%0,%1,%2,%3};"
        : "+f"(c[0]), "+f"(c[1]), "+f"(c[2]), "+f"(c[3])
        : "r"(a0), "r"(a1), "r"(a2), "r"(a3), "r"(b0), "r"(b1));
}
__device__ __forceinline__ void mma_f16(float* c,
    uint32_t a0, uint32_t a1, uint32_t a2, uint32_t a3, uint32_t b0, uint32_t b1) {
    asm volatile(
        "mma.sync.aligned.m16n8k16.row.col.f32.f16.f16.f32 "
        "{%0,%1,%2,%3},{%4,%5,%6,%7},{%8,%9},{%0,%1,%2,%3};"
        : "+f"(c[0]), "+f"(c[1]), "+f"(c[2]), "+f"(c[3])
        : "r"(a0), "r"(a1), "r"(a2), "r"(a3), "r"(b0), "r"(b1));
}
#define LDM4(r0, r1, r2, r3, a)                                          \
    asm volatile("ldmatrix.sync.aligned.m8n8.x4.shared.b16 "             \
                 "{%0,%1,%2,%3},[%4];"                                   \
                 : "=r"(r0), "=r"(r1), "=r"(r2), "=r"(r3) : "r"(a))
#define LDM4T(r0, r1, r2, r3, a)                                         \
    asm volatile("ldmatrix.sync.aligned.m8n8.x4.trans.shared.b16 "       \
                 "{%0,%1,%2,%3},[%4];"                                   \
                 : "=r"(r0), "=r"(r1), "=r"(r2), "=r"(r3) : "r"(a))
__device__ __forceinline__ uint32_t bf2u(__nv_bfloat162 v) {
    return *reinterpret_cast<uint32_t*>(&v);
}
__device__ __forceinline__ void split2(float a, float b, uint32_t& hi, uint32_t& lo) {
    __nv_bfloat162 h = __floats2bfloat162_rn(a, b);
    __nv_bfloat162 l = __floats2bfloat162_rn(a - __bfloat162float(h.x),
                                             b - __bfloat162float(h.y));
    hi = bf2u(h); lo = bf2u(l);
}
__device__ __forceinline__ uint32_t h2u(__half2 v) {
    return *reinterpret_cast<uint32_t*>(&v);
}
#define CPASYNC16(dst, src) \
    asm volatile("cp.async.cg.shared.global [%0], [%1], 16;" :: "r"(dst), "l"(src))
#define CPCOMMIT() asm volatile("cp.async.commit_group;" ::: "memory")
#define CPWAIT(n)  asm volatile("cp.async.wait_group %0;" :: "n"(n) : "memory")
__device__ __forceinline__ uint32_t smem_u32(const void* p) {
    uint32_t a;
    asm("{ .reg .u64 t; cvta.to.shared.u64 t, %1; cvt.u32.u64 %0, t; }"
        : "=r"(a) : "l"(p));
    return a;
}

// ---------------------------------------------------------------------------
// K1: h = X @ W (bf16 hi/lo 3-MMA). 64 rows, 256 thr, grid 128.
// PIPELINED: register-prefetch LDG for chunk c+1 + double-buffered smem
// tiles + ONE barrier per chunk. Inline W split (no prep kernel).
// ---------------------------------------------------------------------------
#define GXH 0
#define GXL 9216
#define GWH 18432
#define GWL 35840
#define GBUF 53248                  // per-buffer stride
#define GA1 106496
#define GA2 107008
#define GSM 107520

__global__ __launch_bounds__(256) void k_gemm_tc(const float* __restrict__ X,
                                                 const float* __restrict__ W,
                                                 const float* __restrict__ a1,
                                                 const float* __restrict__ a2) {
    extern __shared__ char sm[];
    const uint32_t smb = smem_u32(sm);
    const int t = threadIdx.x, w = t >> 5, lane = t & 31;
    const int wm = w & 3, wn = w >> 2;
    const int row0 = blockIdx.x * 64;

    if (t < 128) {
        ((float*)(sm + GA1))[t] = a1[t];
        ((float*)(sm + GA2))[t] = a2[t];
    }

    float acc[8][4];
#pragma unroll
    for (int nt = 0; nt < 8; nt++)
        acc[nt][0] = acc[nt][1] = acc[nt][2] = acc[nt][3] = 0.f;

    const uint32_t ax_off =
        (uint32_t)(wm * 16 + ((lane >> 3) & 1) * 8 + (lane & 7)) * PX +
        (lane >> 4) * 16;
    const uint32_t wl_row = (uint32_t)lane * PW;

    // per-thread load indices (fixed across chunks)
    const int xm = t >> 4, xkq = (t & 15) * 4;          // X: 4 rows apart per l
    const int wk = t >> 5, wnq = (t & 31) * 4;          // W: 8 k apart per l

    float4 xq[4], wq[8];
    auto load_regs = [&](int c) {
        const int kc = c * 64;
#pragma unroll
        for (int l = 0; l < 4; l++)
            xq[l] = *(const float4*)(X + (size_t)(row0 + xm + l * 16) * FIN_ + kc + xkq);
#pragma unroll
        for (int l = 0; l < 8; l++)
            wq[l] = *(const float4*)(W + (size_t)(kc + wk + l * 8) * FOUT_ + wnq);
    };
    auto split_store = [&](int buf) {
        char* base = sm + buf * GBUF;
#pragma unroll
        for (int l = 0; l < 4; l++) {
            uint32_t h0, l0, h1, l1;
            split2(xq[l].x, xq[l].y, h0, l0);
            split2(xq[l].z, xq[l].w, h1, l1);
            uint32_t off = (uint32_t)(xm + l * 16) * PX + xkq * 2;
            *(uint2*)(base + GXH + off) = make_uint2(h0, h1);
            *(uint2*)(base + GXL + off) = make_uint2(l0, l1);
        }
#pragma unroll
        for (int l = 0; l < 8; l++) {
            uint32_t h0, l0, h1, l1;
            split2(wq[l].x, wq[l].y, h0, l0);
            split2(wq[l].z, wq[l].w, h1, l1);
            uint32_t off = (uint32_t)(wk + l * 8) * PW + wnq * 2;
            *(uint2*)(base + GWH + off) = make_uint2(h0, h1);
            *(uint2*)(base + GWL + off) = make_uint2(l0, l1);
        }
    };

    load_regs(0);
    split_store(0);
    __syncthreads();

    for (int c = 0; c < 8; c++) {
        const int buf = c & 1;
        if (c + 1 < 8) load_regs(c + 1);   // LDG latency hidden under MMAs

        const uint32_t bb0 = smb + buf * GBUF;
        uint32_t ah[4][4], al[4][4];
#pragma unroll
        for (int ks = 0; ks < 4; ks++) {
            LDM4(ah[ks][0], ah[ks][1], ah[ks][2], ah[ks][3],
                 bb0 + GXH + ax_off + ks * 32);
            LDM4(al[ks][0], al[ks][1], al[ks][2], al[ks][3],
                 bb0 + GXL + ax_off + ks * 32);
        }
#pragma unroll
        for (int nt = 0; nt < 8; nt++) {
            const int n0 = wn * 64 + nt * 8;
            const uint32_t wadr = bb0 + GWH + wl_row + n0 * 2;
            uint32_t bh[8], bl[8];
            LDM4T(bh[0], bh[1], bh[2], bh[3], wadr);
            LDM4T(bh[4], bh[5], bh[6], bh[7], wadr + 32 * PW);
            LDM4T(bl[0], bl[1], bl[2], bl[3], wadr + (GWL - GWH));
            LDM4T(bl[4], bl[5], bl[6], bl[7], wadr + (GWL - GWH) + 32 * PW);
#pragma unroll
            for (int ks = 0; ks < 4; ks++) {
                mma_bf16(acc[nt], ah[ks][0], ah[ks][1], ah[ks][2], ah[ks][3],
                         bh[2 * ks], bh[2 * ks + 1]);
                mma_bf16(acc[nt], ah[ks][0], ah[ks][1], ah[ks][2], ah[ks][3],
                         bl[2 * ks], bl[2 * ks + 1]);
                mma_bf16(acc[nt], al[ks][0], al[ks][1], al[ks][2], al[ks][3],
                         bh[2 * ks], bh[2 * ks + 1]);
            }
        }

        if (c + 1 < 8) split_store(buf ^ 1);   // writes other buffer
        __syncthreads();                        // buf^1 ready; buf drained
    }

    // ---- epilogue (R13 verbatim) ----
    const int g = lane >> 2, tig = lane & 3;
    float* Ds = (float*)sm;
    {
        const int r = wm * 16 + g, cl = wn * 64 + 2 * tig;
#pragma unroll
        for (int nt = 0; nt < 8; nt++) {
            Ds[r * 132 + cl + nt * 8]           = acc[nt][0];
            Ds[r * 132 + cl + nt * 8 + 1]       = acc[nt][1];
            Ds[(r + 8) * 132 + cl + nt * 8]     = acc[nt][2];
            Ds[(r + 8) * 132 + cl + nt * 8 + 1] = acc[nt][3];
        }
    }
    __syncthreads();
    const float* A1 = (const float*)(sm + GA1);
    const float* A2 = (const float*)(sm + GA2);
#pragma unroll
    for (int rr = 0; rr < 8; rr++) {
        int r = w * 8 + rr;
        float s1 = 0.f, s2 = 0.f;
#pragma unroll
        for (int q = 0; q < 4; q++) {
            float v = Ds[r * 132 + lane + 32 * q];
            s1 = fmaf(v, A1[lane + 32 * q], s1);
            s2 = fmaf(v, A2[lane + 32 * q], s2);
        }
#pragma unroll
        for (int o = 16; o; o >>= 1) {
            s1 += __shfl_down_sync(0xffffffffu, s1, o);
            s2 += __shfl_down_sync(0xffffffffu, s2, o);
        }
        if (lane == 0) {
            int gr = row0 + r;
            g_t1[gr] = s1;  g_t2[gr] = s2;
            g_e1h[gr] = __float2half_rn(0.25f * expf(s1));
            g_f1h[gr] = __float2half_rn(0.25f * expf(0.2f * s1));
            g_e2h[gr] = __float2half_rn(0.25f * expf(s2));
            g_f2h[gr] = __float2half_rn(0.25f * expf(0.2f * s2));
        }
    }
    __syncthreads();
    {
        const int o = t & 127, half = t >> 7;
        const int bb = row0 >> 11, j0g = row0 & (N_ - 1);
        uint32_t uH[16];
#pragma unroll
        for (int ii = 0; ii < 16; ii++) {
            int j0l = half * 32 + 2 * ii;
            uH[ii] = h2u(__floats2half2_rn(Ds[j0l * 132 + o],
                                           Ds[(j0l + 1) * 132 + o]));
        }
        size_t base = ((size_t)(bb * TROWS) + o) * N_ + j0g + half * 32;
#pragma unroll
        for (int q = 0; q < 4; q++)
            *(uint4*)(g_hH + base + q * 8) =
                make_uint4(uH[4 * q], uH[4 * q + 1], uH[4 * q + 2], uH[4 * q + 3]);
        if (t < 64)
            g_hH[((size_t)(bb * TROWS) + 128) * N_ + j0g + t] = __float2half_rn(1.0f);
    }
}

// ---------------------------------------------------------------------------
// K2: attention (R13 verbatim): single fp16-P GEMM [D|den] = P @ [h;1],
// warp grid 2(m) x 4(n), cooperative expand, j-split x2 + in-kernel combine.
// ---------------------------------------------------------------------------
#define ASTG (2 * TILE_B)           // 39168
#define APB  144
#define ASZ  (64 * APB)             // 9216
#define ST2  (ASTG + 2 * ASZ)       // 57600: t2 fp32 [1024]
#define SE2  (ST2 + 4096)           // 61696: 0.25*E2 fp16 [1024]
#define SF2  (SE2 + 2048)           // 63744: 0.25*F2 fp16 [1024]
#define ASM2 (SF2 + 2048)           // 65792 total dynamic

__global__ __launch_bounds__(256, 2) void k_attn_tc(const int* __restrict__ adj,
                                                    const int* __restrict__ d1p,
                                                    const int* __restrict__ d2p,
                                                    float* __restrict__ out) {
    extern __shared__ char sm[];
    __shared__ float s_den[64];
    __shared__ int s_old;
    const uint32_t smb = smem_u32(sm);
    const int t = threadIdx.x, w = t >> 5, lane = t & 31;
    const int g = lane >> 2, tig = lane & 3;
    const int wm = w & 1, wn = w >> 1;
    const int tile = blockIdx.x >> 1, jh = blockIdx.x & 1;
    const int b = tile >> 5, i0 = (tile & 31) * 64;
    const int jbase = jh * 1024;
    const int d1 = *d1p, d2 = *d2p;

    const __half* gHb = g_hH + (size_t)b * TROWS * N_;

    auto load_chunk = [&](int j0, int buf) {
#pragma unroll
        for (int l = 0; l < 5; l++) {
            int f = t + l * 256;
            if (f < 1088) {
                int row = f >> 3, u = f & 7;
                const __half* src = gHb + (size_t)row * N_ + j0 + u * 8;
                uint32_t dst = smb + buf * TILE_B + row * PB2 + u * 16;
                CPASYNC16(dst, src);
            }
        }
    };

    load_chunk(jbase, 0);
    CPCOMMIT();

    // ---- tables into smem ----
    ((float4*)(sm + ST2))[t] = ((const float4*)(g_t2 + b * N_ + jbase))[t];
    if (t < 128)
        ((uint4*)(sm + SE2))[t] = ((const uint4*)(g_e2h + b * N_ + jbase))[t];
    else
        ((uint4*)(sm + SF2))[t - 128] =
            ((const uint4*)(g_f2h + b * N_ + jbase))[t - 128];

    // ---- expansion row constants ----
    const int rexp = t >> 2, ctexp = t & 3;
    const int gadj = b * N_ + i0 + rexp;
    const float nt1r = -g_t1[gadj];
    const uint32_t e1lo = (uint32_t)__half_as_ushort(g_e1h[gadj]);
    const uint32_t f1lo = (uint32_t)__half_as_ushort(g_f1h[gadj]);
    const uint32_t e1hi = e1lo << 16, f1hi = f1lo << 16;
    const int* adjrow = adj + (size_t)gadj * N_ + jbase + ctexp * 16;

    auto expand = [&](int4 q0, int4 q1, int4 q2, int4 q3, int cc, int ab) {
        const int jl = cc * 64 + ctexp * 16;
        const float* tp = (const float*)(sm + ST2) + jl;
        float4 t0 = *(const float4*)(tp);
        float4 t1v = *(const float4*)(tp + 4);
        float4 t2v = *(const float4*)(tp + 8);
        float4 t3 = *(const float4*)(tp + 12);
        float tf[16] = {t0.x, t0.y, t0.z, t0.w, t1v.x, t1v.y, t1v.z, t1v.w,
                        t2v.x, t2v.y, t2v.z, t2v.w, t3.x, t3.y, t3.z, t3.w};
        uint4 ea = *(const uint4*)((const __half*)(sm + SE2) + jl);
        uint4 eb = *(const uint4*)((const __half*)(sm + SE2) + jl + 8);
        uint4 fa = *(const uint4*)((const __half*)(sm + SF2) + jl);
        uint4 fb = *(const uint4*)((const __half*)(sm + SF2) + jl + 8);
        uint32_t UE[8] = {ea.x, ea.y, ea.z, ea.w, eb.x, eb.y, eb.z, eb.w};
        uint32_t UF[8] = {fa.x, fa.y, fa.z, fa.w, fb.x, fb.y, fb.z, fb.w};
        int av[16] = {q0.x, q0.y, q0.z, q0.w, q1.x, q1.y, q1.z, q1.w,
                      q2.x, q2.y, q2.z, q2.w, q3.x, q3.y, q3.z, q3.w};
        uint32_t ow[8];
#pragma unroll
        for (int k = 0; k < 8; k++) {
            int a0 = av[2 * k], a1 = av[2 * k + 1];
            bool m0 = (a0 == d1) | (a0 == d2);
            bool m1 = (a1 == d1) | (a1 == d2);
            bool p0 = tf[2 * k] > nt1r;
            bool p1 = tf[2 * k + 1] > nt1r;
            uint32_t s2 = (p0 ? (UE[k] & 0xffffu) : (UF[k] & 0xffffu))
                        | (p1 ? (UE[k] & 0xffff0000u) : (UF[k] & 0xffff0000u));
            uint32_t s1 = (p0 ? e1lo : f1lo) | (p1 ? e1hi : f1hi);
            __half2 pr = __hmul2(*(__half2*)&s1, *(__half2*)&s2);
            uint32_t z = (m0 ? 0xffffu : 0u) | (m1 ? 0xffff0000u : 0u);
            ow[k] = (*(uint32_t*)&pr) & z;
        }
        char* dst = sm + ASTG + ab * ASZ + rexp * APB + ctexp * 32;
        *(uint4*)(dst)      = make_uint4(ow[0], ow[1], ow[2], ow[3]);
        *(uint4*)(dst + 16) = make_uint4(ow[4], ow[5], ow[6], ow[7]);
    };

    int4 q0 = *(const int4*)(adjrow);
    int4 q1 = *(const int4*)(adjrow + 4);
    int4 q2 = *(const int4*)(adjrow + 8);
    int4 q3 = *(const int4*)(adjrow + 12);

    __syncthreads();
    expand(q0, q1, q2, q3, 0, 0);

    const int ntiles = (wn == 3) ? 5 : 4;
    float acc[2][5][4];
#pragma unroll
    for (int ms = 0; ms < 2; ms++)
#pragma unroll
        for (int k = 0; k < 5; k++)
            acc[ms][k][0] = acc[ms][k][1] = acc[ms][k][2] = acc[ms][k][3] = 0.f;

    const uint32_t bloff = (uint32_t)(lane & 7) * PB2 + (lane >> 3) * 16;
    const uint32_t aloff =
        (uint32_t)((lane & 15) + wm * 32) * APB + (lane >> 4) * 16;

    for (int c = 0; c < 16; c++) {
        const int buf = c & 1;
        CPWAIT(0);
        __syncthreads();
        if (c + 1 < 16) {
            load_chunk(jbase + (c + 1) * 64, buf ^ 1);
            CPCOMMIT();
            const int* ap = adjrow + (c + 1) * 64;
            q0 = *(const int4*)(ap);
            q1 = *(const int4*)(ap + 4);
            q2 = *(const int4*)(ap + 8);
            q3 = *(const int4*)(ap + 12);
        }

        const uint32_t abase = smb + ASTG + buf * ASZ + aloff;
        const uint32_t base = smb + buf * TILE_B + bloff;
#pragma unroll
        for (int ga = 0; ga < 2; ga++) {
            uint32_t aH[2][2][4];
#pragma unroll
            for (int ms = 0; ms < 2; ms++)
#pragma unroll
                for (int k2 = 0; k2 < 2; k2++)
                    LDM4(aH[ms][k2][0], aH[ms][k2][1], aH[ms][k2][2], aH[ms][k2][3],
                         abase + (uint32_t)(ms * 16) * APB + (2 * ga + k2) * 32);

            uint32_t bb[2][4];
            {
                const int gt0 = wn * 4;
                LDM4(bb[0][0], bb[0][1], bb[0][2], bb[0][3],
                     base + (uint32_t)(gt0 * 8) * PB2 + ga * 64);
            }
#pragma unroll
            for (int k = 0; k < 5; k++) {
                if (k >= ntiles) break;
                const int cur = k & 1, nxt = cur ^ 1;
                if (k + 1 < ntiles) {
                    const int gtn = (k + 1 < 4) ? wn * 4 + k + 1 : 16;
                    LDM4(bb[nxt][0], bb[nxt][1], bb[nxt][2], bb[nxt][3],
                         base + (uint32_t)(gtn * 8) * PB2 + ga * 64);
                }
                mma_f16(acc[0][k], aH[0][0][0], aH[0][0][1], aH[0][0][2], aH[0][0][3],
                        bb[cur][0], bb[cur][1]);
                mma_f16(acc[1][k], aH[1][0][0], aH[1][0][1], aH[1][0][2], aH[1][0][3],
                        bb[cur][0], bb[cur][1]);
                mma_f16(acc[0][k], aH[0][1][0], aH[0][1][1], aH[0][1][2], aH[0][1][3],
                        bb[cur][2], bb[cur][3]);
                mma_f16(acc[1][k], aH[1][1][0], aH[1][1][1], aH[1][1][2], aH[1][1][3],
                        bb[cur][2], bb[cur][3]);
            }
        }

        if (c + 1 < 16)
            expand(q0, q1, q2, q3, c + 1, buf ^ 1);
    }

    if (wn == 3 && tig == 0) {
#pragma unroll
        for (int ms = 0; ms < 2; ms++) {
            s_den[wm * 32 + ms * 16 + g]     = acc[ms][4][0];
            s_den[wm * 32 + ms * 16 + g + 8] = acc[ms][4][2];
        }
    }
    __syncthreads();

    float* gp = g_part[jh];
#pragma unroll
    for (int ms = 0; ms < 2; ms++) {
        const int gr0 = b * N_ + i0 + wm * 32 + ms * 16 + g;
        const int gr1 = gr0 + 8;
#pragma unroll
        for (int k = 0; k < 4; k++) {
            const int cl = (wn * 4 + k) * 8 + 2 * tig;
            *(float2*)(gp + (size_t)gr0 * FOUT_ + cl) =
                make_float2(acc[ms][k][0], acc[ms][k][1]);
            *(float2*)(gp + (size_t)gr1 * FOUT_ + cl) =
                make_float2(acc[ms][k][2], acc[ms][k][3]);
        }
    }
    if (t < 64) g_den[jh][b * N_ + i0 + t] = s_den[t];
    __threadfence();
    __syncthreads();
    if (t == 0) s_old = atomicAdd(&g_cnt[tile], 1);
    __syncthreads();

    if (s_old == 1) {
        __threadfence();
        const float* go = g_part[jh ^ 1];
        const float* gdo = g_den[jh ^ 1];
#pragma unroll
        for (int ms = 0; ms < 2; ms++) {
            const int lr0 = wm * 32 + ms * 16 + g;
            const int gr0 = b * N_ + i0 + lr0;
            const int gr1 = gr0 + 8;
            const float inv0 = 1.0f / (s_den[lr0] + gdo[gr0]);
            const float inv1 = 1.0f / (s_den[lr0 + 8] + gdo[gr1]);
#pragma unroll
            for (int k = 0; k < 4; k++) {
                const int cl = (wn * 4 + k) * 8 + 2 * tig;
                float2 o0 = *(const float2*)(go + (size_t)gr0 * FOUT_ + cl);
                float2 o1 = *(const float2*)(go + (size_t)gr1 * FOUT_ + cl);
                *(float2*)(out + (size_t)gr0 * FOUT_ + cl) =
                    make_float2((acc[ms][k][0] + o0.x) * inv0,
                                (acc[ms][k][1] + o0.y) * inv0);
                *(float2*)(out + (size_t)gr1 * FOUT_ + cl) =
                    make_float2((acc[ms][k][2] + o1.x) * inv1,
                                (acc[ms][k][3] + o1.y) * inv1);
            }
        }
        if (t == 0) g_cnt[tile] = 0;
    }
}

// ---------------------------------------------------------------------------
extern "C" void kernel_launch(void* const* d_in, const int* in_sizes, int n_in,
                              void* d_out, int out_size) {
    const float* X   = (const float*)d_in[0];
    const float* W   = (const float*)d_in[1];
    const float* a1  = (const float*)d_in[2];
    const float* a2  = (const float*)d_in[3];
    const int*   adj = (const int*)d_in[4];
    // d_in[5] = adj_tree: unused by the reference forward
    const int* d1p = (const int*)d_in[6];
    const int* d2p = (const int*)d_in[7];
    float* out = (float*)d_out;

    cudaFuncSetAttribute(k_gemm_tc, cudaFuncAttributeMaxDynamicSharedMemorySize, GSM);
    k_gemm_tc<<<ROWS_TOT / 64, 256, GSM>>>(X, W, a1, a2);

    cudaFuncSetAttribute(k_attn_tc, cudaFuncAttributeMaxDynamicSharedMemorySize, ASM2);
    k_attn_tc<<<B_ * 32 * 2, 256, ASM2>>>(adj, d1p, d2p, out);
}

// round 17
// speedup vs baseline: 1.0909x; 1.0005x over previous
#include <cuda_runtime.h>
#include <cuda_bf16.h>
#include <cuda_fp16.h>
#include <cstdint>

#define B_    4
#define N_    2048
#define FIN_  512
#define FOUT_ 128
#define ROWS_TOT (B_ * N_)
#define PX    144
#define PW    272
#define PB2   144    // attn B tile pitch
#define TROWS 136    // 128 h rows + 1 ones row + 7 zero pad
#define TILE_B (TROWS * PB2)   // 19584

// ---------------- global scratch (no cudaMalloc allowed) --------------------
__device__ __align__(16) __half g_hH[B_ * TROWS * N_];  // [b][o][j] h fp16; row128=1
__device__ __align__(16) __half g_e2h[ROWS_TOT], g_f2h[ROWS_TOT];  // 0.25*E2/F2
__device__ __half g_e1h[ROWS_TOT], g_f1h[ROWS_TOT];                // 0.25*E1/F1
__device__ float g_t1[ROWS_TOT], g_t2[ROWS_TOT];
__device__ __align__(16) float g_part[2][ROWS_TOT * FOUT_];
__device__ float g_den[2][ROWS_TOT];
__device__ int   g_cnt[B_ * 32];

// ---------------- helpers ----------------------------------------------------
__device__ __forceinline__ void mma_bf16(float* c,
    uint32_t a0, uint32_t a1, uint32_t a2, uint32_t a3, uint32_t b0, uint32_t b1) {
    asm volatile(
        "mma.sync.aligned.m16n8k16.row.col.f32.bf16.bf16.f32 "
        "{%0,%1,%2,%3},{%4,%5,%6,%7},{%8,%9},{%0,%1,%2,%3};"
        : "+f"(c[0]), "+f"(c[1]), "+f"(c[2]), "+f"(c[3])
        : "r"(a0), "r"(a1), "r"(a2), "r"(a3), "r"(b0), "r"(b1));
}
__device__ __forceinline__ void mma_f16(float* c,
    uint32_t a0, uint32_t a1, uint32_t a2, uint32_t a3, uint32_t b0, uint32_t b1) {
    asm volatile(
        "mma.sync.aligned.m16n8k16.row.col.f32.f16.f16.f32 "
        "{%0,%1,%2,%3},{%4,%5,%6,%7},{%8,%9},{%0,%1,%2,%3};"
        : "+f"(c[0]), "+f"(c[1]), "+f"(c[2]), "+f"(c[3])
        : "r"(a0), "r"(a1), "r"(a2), "r"(a3), "r"(b0), "r"(b1));
}
#define LDM4(r0, r1, r2, r3, a)                                          \
    asm volatile("ldmatrix.sync.aligned.m8n8.x4.shared.b16 "             \
                 "{%0,%1,%2,%3},[%4];"                                   \
                 : "=r"(r0), "=r"(r1), "=r"(r2), "=r"(r3) : "r"(a))
#define LDM4T(r0, r1, r2, r3, a)                                         \
    asm volatile("ldmatrix.sync.aligned.m8n8.x4.trans.shared.b16 "       \
                 "{%0,%1,%2,%3},[%4];"                                   \
                 : "=r"(r0), "=r"(r1), "=r"(r2), "=r"(r3) : "r"(a))
__device__ __forceinline__ uint32_t bf2u(__nv_bfloat162 v) {
    return *reinterpret_cast<uint32_t*>(&v);
}
__device__ __forceinline__ void split2(float a, float b, uint32_t& hi, uint32_t& lo) {
    __nv_bfloat162 h = __floats2bfloat162_rn(a, b);
    __nv_bfloat162 l = __floats2bfloat162_rn(a - __bfloat162float(h.x),
                                             b - __bfloat162float(h.y));
    hi = bf2u(h); lo = bf2u(l);
}
__device__ __forceinline__ uint32_t h2u(__half2 v) {
    return *reinterpret_cast<uint32_t*>(&v);
}
#define CPASYNC16(dst, src) \
    asm volatile("cp.async.cg.shared.global [%0], [%1], 16;" :: "r"(dst), "l"(src))
#define CPCOMMIT() asm volatile("cp.async.commit_group;" ::: "memory")
#define CPWAIT(n)  asm volatile("cp.async.wait_group %0;" :: "n"(n) : "memory")
__device__ __forceinline__ uint32_t smem_u32(const void* p) {
    uint32_t a;
    asm("{ .reg .u64 t; cvta.to.shared.u64 t, %1; cvt.u32.u64 %0, t; }"
        : "=r"(a) : "l"(p));
    return a;
}

// ---------------------------------------------------------------------------
// K1: h = X @ W (bf16 hi/lo 3-MMA). 64 rows, 256 thr, grid 128.
// Pipelined (reg prefetch + double-buffered smem, 1 barrier/chunk).
// Warp grid 2(m) x 4(n): halves redundant W-fragment ldmatrix traffic.
// ---------------------------------------------------------------------------
#define GXH 0
#define GXL 9216
#define GWH 18432
#define GWL 35840
#define GBUF 53248                  // per-buffer stride
#define GA1 106496
#define GA2 107008
#define GSM 107520

__global__ __launch_bounds__(256) void k_gemm_tc(const float* __restrict__ X,
                                                 const float* __restrict__ W,
                                                 const float* __restrict__ a1,
                                                 const float* __restrict__ a2) {
    extern __shared__ char sm[];
    const uint32_t smb = smem_u32(sm);
    const int t = threadIdx.x, w = t >> 5, lane = t & 31;
    const int wm = w & 1, wn = w >> 1;          // 2m x 4n
    const int row0 = blockIdx.x * 64;

    if (t < 128) {
        ((float*)(sm + GA1))[t] = a1[t];
        ((float*)(sm + GA2))[t] = a2[t];
    }

    float acc[2][4][4];                          // [m-set][n-tile][frag]
#pragma unroll
    for (int ms = 0; ms < 2; ms++)
#pragma unroll
        for (int k = 0; k < 4; k++)
            acc[ms][k][0] = acc[ms][k][1] = acc[ms][k][2] = acc[ms][k][3] = 0.f;

    // A frag base: rows wm*32 + ms*16 + lane-derived
    const uint32_t ax_off =
        (uint32_t)(wm * 32 + ((lane >> 3) & 1) * 8 + (lane & 7)) * PX +
        (lane >> 4) * 16;
    const uint32_t wl_row = (uint32_t)lane * PW;

    // per-thread load indices (fixed across chunks)
    const int xm = t >> 4, xkq = (t & 15) * 4;
    const int wk = t >> 5, wnq = (t & 31) * 4;

    float4 xq[4], wq[8];
    auto load_regs = [&](int c) {
        const int kc = c * 64;
#pragma unroll
        for (int l = 0; l < 4; l++)
            xq[l] = *(const float4*)(X + (size_t)(row0 + xm + l * 16) * FIN_ + kc + xkq);
#pragma unroll
        for (int l = 0; l < 8; l++)
            wq[l] = *(const float4*)(W + (size_t)(kc + wk + l * 8) * FOUT_ + wnq);
    };
    auto split_store = [&](int buf) {
        char* base = sm + buf * GBUF;
#pragma unroll
        for (int l = 0; l < 4; l++) {
            uint32_t h0, l0, h1, l1;
            split2(xq[l].x, xq[l].y, h0, l0);
            split2(xq[l].z, xq[l].w, h1, l1);
            uint32_t off = (uint32_t)(xm + l * 16) * PX + xkq * 2;
            *(uint2*)(base + GXH + off) = make_uint2(h0, h1);
            *(uint2*)(base + GXL + off) = make_uint2(l0, l1);
        }
#pragma unroll
        for (int l = 0; l < 8; l++) {
            uint32_t h0, l0, h1, l1;
            split2(wq[l].x, wq[l].y, h0, l0);
            split2(wq[l].z, wq[l].w, h1, l1);
            uint32_t off = (uint32_t)(wk + l * 8) * PW + wnq * 2;
            *(uint2*)(base + GWH + off) = make_uint2(h0, h1);
            *(uint2*)(base + GWL + off) = make_uint2(l0, l1);
        }
    };

    load_regs(0);
    split_store(0);
    __syncthreads();

    for (int c = 0; c < 8; c++) {
        const int buf = c & 1;
        if (c + 1 < 8) load_regs(c + 1);   // LDG latency hidden under MMAs

        const uint32_t bb0 = smb + buf * GBUF;
#pragma unroll
        for (int ga = 0; ga < 2; ga++) {
            // A frags: 2 m-sets x 2 k-steps, hi + lo
            uint32_t ah[2][2][4], al[2][2][4];
#pragma unroll
            for (int ms = 0; ms < 2; ms++)
#pragma unroll
                for (int k2 = 0; k2 < 2; k2++) {
                    const uint32_t a = bb0 + ax_off + (uint32_t)(ms * 16) * PX +
                                       (2 * ga + k2) * 32;
                    LDM4(ah[ms][k2][0], ah[ms][k2][1], ah[ms][k2][2], ah[ms][k2][3],
                         a + GXH);
                    LDM4(al[ms][k2][0], al[ms][k2][1], al[ms][k2][2], al[ms][k2][3],
                         a + GXL);
                }
            // B frags: my 4 n-tiles, k-rows ga*32..ga*32+31 (2 k-steps)
#pragma unroll
            for (int k = 0; k < 4; k++) {
                const int n0 = (wn * 4 + k) * 8;
                const uint32_t wadr = bb0 + wl_row + (uint32_t)ga * 32 * PW + n0 * 2;
                uint32_t bh[4], bl[4];
                LDM4T(bh[0], bh[1], bh[2], bh[3], wadr + GWH);
                LDM4T(bl[0], bl[1], bl[2], bl[3], wadr + GWL);
#pragma unroll
                for (int ms = 0; ms < 2; ms++)
#pragma unroll
                    for (int k2 = 0; k2 < 2; k2++) {
                        mma_bf16(acc[ms][k],
                                 ah[ms][k2][0], ah[ms][k2][1],
                                 ah[ms][k2][2], ah[ms][k2][3],
                                 bh[2 * k2], bh[2 * k2 + 1]);
                        mma_bf16(acc[ms][k],
                                 ah[ms][k2][0], ah[ms][k2][1],
                                 ah[ms][k2][2], ah[ms][k2][3],
                                 bl[2 * k2], bl[2 * k2 + 1]);
                        mma_bf16(acc[ms][k],
                                 al[ms][k2][0], al[ms][k2][1],
                                 al[ms][k2][2], al[ms][k2][3],
                                 bh[2 * k2], bh[2 * k2 + 1]);
                    }
            }
        }

        if (c + 1 < 8) split_store(buf ^ 1);
        __syncthreads();
    }

    // ---- epilogue ----
    const int g = lane >> 2, tig = lane & 3;
    float* Ds = (float*)sm;
    {
#pragma unroll
        for (int ms = 0; ms < 2; ms++) {
            const int r = wm * 32 + ms * 16 + g;
#pragma unroll
            for (int k = 0; k < 4; k++) {
                const int cl = (wn * 4 + k) * 8 + 2 * tig;
                Ds[r * 132 + cl]           = acc[ms][k][0];
                Ds[r * 132 + cl + 1]       = acc[ms][k][1];
                Ds[(r + 8) * 132 + cl]     = acc[ms][k][2];
                Ds[(r + 8) * 132 + cl + 1] = acc[ms][k][3];
            }
        }
    }
    __syncthreads();
    const float* A1 = (const float*)(sm + GA1);
    const float* A2 = (const float*)(sm + GA2);
#pragma unroll
    for (int rr = 0; rr < 8; rr++) {
        int r = w * 8 + rr;
        float s1 = 0.f, s2 = 0.f;
#pragma unroll
        for (int q = 0; q < 4; q++) {
            float v = Ds[r * 132 + lane + 32 * q];
            s1 = fmaf(v, A1[lane + 32 * q], s1);
            s2 = fmaf(v, A2[lane + 32 * q], s2);
        }
#pragma unroll
        for (int o = 16; o; o >>= 1) {
            s1 += __shfl_down_sync(0xffffffffu, s1, o);
            s2 += __shfl_down_sync(0xffffffffu, s2, o);
        }
        if (lane == 0) {
            int gr = row0 + r;
            g_t1[gr] = s1;  g_t2[gr] = s2;
            g_e1h[gr] = __float2half_rn(0.25f * expf(s1));
            g_f1h[gr] = __float2half_rn(0.25f * expf(0.2f * s1));
            g_e2h[gr] = __float2half_rn(0.25f * expf(s2));
            g_f2h[gr] = __float2half_rn(0.25f * expf(0.2f * s2));
        }
    }
    __syncthreads();
    {
        const int o = t & 127, half = t >> 7;
        const int bb = row0 >> 11, j0g = row0 & (N_ - 1);
        uint32_t uH[16];
#pragma unroll
        for (int ii = 0; ii < 16; ii++) {
            int j0l = half * 32 + 2 * ii;
            uH[ii] = h2u(__floats2half2_rn(Ds[j0l * 132 + o],
                                           Ds[(j0l + 1) * 132 + o]));
        }
        size_t base = ((size_t)(bb * TROWS) + o) * N_ + j0g + half * 32;
#pragma unroll
        for (int q = 0; q < 4; q++)
            *(uint4*)(g_hH + base + q * 8) =
                make_uint4(uH[4 * q], uH[4 * q + 1], uH[4 * q + 2], uH[4 * q + 3]);
        if (t < 64)
            g_hH[((size_t)(bb * TROWS) + 128) * N_ + j0g + t] = __float2half_rn(1.0f);
    }
}

// ---------------------------------------------------------------------------
// K2: attention (R13/R16 verbatim): single fp16-P GEMM [D|den] = P @ [h;1],
// warp grid 2(m) x 4(n), cooperative expand, j-split x2 + in-kernel combine.
// ---------------------------------------------------------------------------
#define ASTG (2 * TILE_B)           // 39168
#define APB  144
#define ASZ  (64 * APB)             // 9216
#define ST2  (ASTG + 2 * ASZ)       // 57600: t2 fp32 [1024]
#define SE2  (ST2 + 4096)           // 61696: 0.25*E2 fp16 [1024]
#define SF2  (SE2 + 2048)           // 63744: 0.25*F2 fp16 [1024]
#define ASM2 (SF2 + 2048)           // 65792 total dynamic

__global__ __launch_bounds__(256, 2) void k_attn_tc(const int* __restrict__ adj,
                                                    const int* __restrict__ d1p,
                                                    const int* __restrict__ d2p,
                                                    float* __restrict__ out) {
    extern __shared__ char sm[];
    __shared__ float s_den[64];
    __shared__ int s_old;
    const uint32_t smb = smem_u32(sm);
    const int t = threadIdx.x, w = t >> 5, lane = t & 31;
    const int g = lane >> 2, tig = lane & 3;
    const int wm = w & 1, wn = w >> 1;
    const int tile = blockIdx.x >> 1, jh = blockIdx.x & 1;
    const int b = tile >> 5, i0 = (tile & 31) * 64;
    const int jbase = jh * 1024;
    const int d1 = *d1p, d2 = *d2p;

    const __half* gHb = g_hH + (size_t)b * TROWS * N_;

    auto load_chunk = [&](int j0, int buf) {
#pragma unroll
        for (int l = 0; l < 5; l++) {
            int f = t + l * 256;
            if (f < 1088) {
                int row = f >> 3, u = f & 7;
                const __half* src = gHb + (size_t)row * N_ + j0 + u * 8;
                uint32_t dst = smb + buf * TILE_B + row * PB2 + u * 16;
                CPASYNC16(dst, src);
            }
        }
    };

    load_chunk(jbase, 0);
    CPCOMMIT();

    // ---- tables into smem ----
    ((float4*)(sm + ST2))[t] = ((const float4*)(g_t2 + b * N_ + jbase))[t];
    if (t < 128)
        ((uint4*)(sm + SE2))[t] = ((const uint4*)(g_e2h + b * N_ + jbase))[t];
    else
        ((uint4*)(sm + SF2))[t - 128] =
            ((const uint4*)(g_f2h + b * N_ + jbase))[t - 128];

    // ---- expansion row constants ----
    const int rexp = t >> 2, ctexp = t & 3;
    const int gadj = b * N_ + i0 + rexp;
    const float nt1r = -g_t1[gadj];
    const uint32_t e1lo = (uint32_t)__half_as_ushort(g_e1h[gadj]);
    const uint32_t f1lo = (uint32_t)__half_as_ushort(g_f1h[gadj]);
    const uint32_t e1hi = e1lo << 16, f1hi = f1lo << 16;
    const int* adjrow = adj + (size_t)gadj * N_ + jbase + ctexp * 16;

    auto expand = [&](int4 q0, int4 q1, int4 q2, int4 q3, int cc, int ab) {
        const int jl = cc * 64 + ctexp * 16;
        const float* tp = (const float*)(sm + ST2) + jl;
        float4 t0 = *(const float4*)(tp);
        float4 t1v = *(const float4*)(tp + 4);
        float4 t2v = *(const float4*)(tp + 8);
        float4 t3 = *(const float4*)(tp + 12);
        float tf[16] = {t0.x, t0.y, t0.z, t0.w, t1v.x, t1v.y, t1v.z, t1v.w,
                        t2v.x, t2v.y, t2v.z, t2v.w, t3.x, t3.y, t3.z, t3.w};
        uint4 ea = *(const uint4*)((const __half*)(sm + SE2) + jl);
        uint4 eb = *(const uint4*)((const __half*)(sm + SE2) + jl + 8);
        uint4 fa = *(const uint4*)((const __half*)(sm + SF2) + jl);
        uint4 fb = *(const uint4*)((const __half*)(sm + SF2) + jl + 8);
        uint32_t UE[8] = {ea.x, ea.y, ea.z, ea.w, eb.x, eb.y, eb.z, eb.w};
        uint32_t UF[8] = {fa.x, fa.y, fa.z, fa.w, fb.x, fb.y, fb.z, fb.w};
        int av[16] = {q0.x, q0.y, q0.z, q0.w, q1.x, q1.y, q1.z, q1.w,
                      q2.x, q2.y, q2.z, q2.w, q3.x, q3.y, q3.z, q3.w};
        uint32_t ow[8];
#pragma unroll
        for (int k = 0; k < 8; k++) {
            int a0 = av[2 * k], a1 = av[2 * k + 1];
            bool m0 = (a0 == d1) | (a0 == d2);
            bool m1 = (a1 == d1) | (a1 == d2);
            bool p0 = tf[2 * k] > nt1r;
            bool p1 = tf[2 * k + 1] > nt1r;
            uint32_t s2 = (p0 ? (UE[k] & 0xffffu) : (UF[k] & 0xffffu))
                        | (p1 ? (UE[k] & 0xffff0000u) : (UF[k] & 0xffff0000u));
            uint32_t s1 = (p0 ? e1lo : f1lo) | (p1 ? e1hi : f1hi);
            __half2 pr = __hmul2(*(__half2*)&s1, *(__half2*)&s2);
            uint32_t z = (m0 ? 0xffffu : 0u) | (m1 ? 0xffff0000u : 0u);
            ow[k] = (*(uint32_t*)&pr) & z;
        }
        char* dst = sm + ASTG + ab * ASZ + rexp * APB + ctexp * 32;
        *(uint4*)(dst)      = make_uint4(ow[0], ow[1], ow[2], ow[3]);
        *(uint4*)(dst + 16) = make_uint4(ow[4], ow[5], ow[6], ow[7]);
    };

    int4 q0 = *(const int4*)(adjrow);
    int4 q1 = *(const int4*)(adjrow + 4);
    int4 q2 = *(const int4*)(adjrow + 8);
    int4 q3 = *(const int4*)(adjrow + 12);

    __syncthreads();
    expand(q0, q1, q2, q3, 0, 0);

    const int ntiles = (wn == 3) ? 5 : 4;
    float acc[2][5][4];
#pragma unroll
    for (int ms = 0; ms < 2; ms++)
#pragma unroll
        for (int k = 0; k < 5; k++)
            acc[ms][k][0] = acc[ms][k][1] = acc[ms][k][2] = acc[ms][k][3] = 0.f;

    const uint32_t bloff = (uint32_t)(lane & 7) * PB2 + (lane >> 3) * 16;
    const uint32_t aloff =
        (uint32_t)((lane & 15) + wm * 32) * APB + (lane >> 4) * 16;

    for (int c = 0; c < 16; c++) {
        const int buf = c & 1;
        CPWAIT(0);
        __syncthreads();
        if (c + 1 < 16) {
            load_chunk(jbase + (c + 1) * 64, buf ^ 1);
            CPCOMMIT();
            const int* ap = adjrow + (c + 1) * 64;
            q0 = *(const int4*)(ap);
            q1 = *(const int4*)(ap + 4);
            q2 = *(const int4*)(ap + 8);
            q3 = *(const int4*)(ap + 12);
        }

        const uint32_t abase = smb + ASTG + buf * ASZ + aloff;
        const uint32_t base = smb + buf * TILE_B + bloff;
#pragma unroll
        for (int ga = 0; ga < 2; ga++) {
            uint32_t aH[2][2][4];
#pragma unroll
            for (int ms = 0; ms < 2; ms++)
#pragma unroll
                for (int k2 = 0; k2 < 2; k2++)
                    LDM4(aH[ms][k2][0], aH[ms][k2][1], aH[ms][k2][2], aH[ms][k2][3],
                         abase + (uint32_t)(ms * 16) * APB + (2 * ga + k2) * 32);

            uint32_t bb[2][4];
            {
                const int gt0 = wn * 4;
                LDM4(bb[0][0], bb[0][1], bb[0][2], bb[0][3],
                     base + (uint32_t)(gt0 * 8) * PB2 + ga * 64);
            }
#pragma unroll
            for (int k = 0; k < 5; k++) {
                if (k >= ntiles) break;
                const int cur = k & 1, nxt = cur ^ 1;
                if (k + 1 < ntiles) {
                    const int gtn = (k + 1 < 4) ? wn * 4 + k + 1 : 16;
                    LDM4(bb[nxt][0], bb[nxt][1], bb[nxt][2], bb[nxt][3],
                         base + (uint32_t)(gtn * 8) * PB2 + ga * 64);
                }
                mma_f16(acc[0][k], aH[0][0][0], aH[0][0][1], aH[0][0][2], aH[0][0][3],
                        bb[cur][0], bb[cur][1]);
                mma_f16(acc[1][k], aH[1][0][0], aH[1][0][1], aH[1][0][2], aH[1][0][3],
                        bb[cur][0], bb[cur][1]);
                mma_f16(acc[0][k], aH[0][1][0], aH[0][1][1], aH[0][1][2], aH[0][1][3],
                        bb[cur][2], bb[cur][3]);
                mma_f16(acc[1][k], aH[1][1][0], aH[1][1][1], aH[1][1][2], aH[1][1][3],
                        bb[cur][2], bb[cur][3]);
            }
        }

        if (c + 1 < 16)
            expand(q0, q1, q2, q3, c + 1, buf ^ 1);
    }

    if (wn == 3 && tig == 0) {
#pragma unroll
        for (int ms = 0; ms < 2; ms++) {
            s_den[wm * 32 + ms * 16 + g]     = acc[ms][4][0];
            s_den[wm * 32 + ms * 16 + g + 8] = acc[ms][4][2];
        }
    }
    __syncthreads();

    float* gp = g_part[jh];
#pragma unroll
    for (int ms = 0; ms < 2; ms++) {
        const int gr0 = b * N_ + i0 + wm * 32 + ms * 16 + g;
        const int gr1 = gr0 + 8;
#pragma unroll
        for (int k = 0; k < 4; k++) {
            const int cl = (wn * 4 + k) * 8 + 2 * tig;
            *(float2*)(gp + (size_t)gr0 * FOUT_ + cl) =
                make_float2(acc[ms][k][0], acc[ms][k][1]);
            *(float2*)(gp + (size_t)gr1 * FOUT_ + cl) =
                make_float2(acc[ms][k][2], acc[ms][k][3]);
        }
    }
    if (t < 64) g_den[jh][b * N_ + i0 + t] = s_den[t];
    __threadfence();
    __syncthreads();
    if (t == 0) s_old = atomicAdd(&g_cnt[tile], 1);
    __syncthreads();

    if (s_old == 1) {
        __threadfence();
        const float* go = g_part[jh ^ 1];
        const float* gdo = g_den[jh ^ 1];
#pragma unroll
        for (int ms = 0; ms < 2; ms++) {
            const int lr0 = wm * 32 + ms * 16 + g;
            const int gr0 = b * N_ + i0 + lr0;
            const int gr1 = gr0 + 8;
            const float inv0 = 1.0f / (s_den[lr0] + gdo[gr0]);
            const float inv1 = 1.0f / (s_den[lr0 + 8] + gdo[gr1]);
#pragma unroll
            for (int k = 0; k < 4; k++) {
                const int cl = (wn * 4 + k) * 8 + 2 * tig;
                float2 o0 = *(const float2*)(go + (size_t)gr0 * FOUT_ + cl);
                float2 o1 = *(const float2*)(go + (size_t)gr1 * FOUT_ + cl);
                *(float2*)(out + (size_t)gr0 * FOUT_ + cl) =
                    make_float2((acc[ms][k][0] + o0.x) * inv0,
                                (acc[ms][k][1] + o0.y) * inv0);
                *(float2*)(out + (size_t)gr1 * FOUT_ + cl) =
                    make_float2((acc[ms][k][2] + o1.x) * inv1,
                                (acc[ms][k][3] + o1.y) * inv1);
            }
        }
        if (t == 0) g_cnt[tile] = 0;
    }
}

// ---------------------------------------------------------------------------
extern "C" void kernel_launch(void* const* d_in, const int* in_sizes, int n_in,
                              void* d_out, int out_size) {
    const float* X   = (const float*)d_in[0];
    const float* W   = (const float*)d_in[1];
    const float* a1  = (const float*)d_in[2];
    const float* a2  = (const float*)d_in[3];
    const int*   adj = (const int*)d_in[4];
    // d_in[5] = adj_tree: unused by the reference forward
    const int* d1p = (const int*)d_in[6];
    const int* d2p = (const int*)d_in[7];
    float* out = (float*)d_out;

    cudaFuncSetAttribute(k_gemm_tc, cudaFuncAttributeMaxDynamicSharedMemorySize, GSM);
    k_gemm_tc<<<ROWS_TOT / 64, 256, GSM>>>(X, W, a1, a2);

    cudaFuncSetAttribute(k_attn_tc, cudaFuncAttributeMaxDynamicSharedMemorySize, ASM2);
    k_attn_tc<<<B_ * 32 * 2, 256, ASM2>>>(adj, d1p, d2p, out);
}